// round 2
// baseline (speedup 1.0000x reference)
#include <cuda_runtime.h>
#include <cuda_bf16.h>
#include <cstdint>

// Problem constants (fixed by the reference)
#define NUM_USERS 50000
#define NUM_ITEMS 50000
#define N_NODES   (NUM_USERS + NUM_ITEMS)   // 100000
#define EMB_DIM   64
#define N_LAYERS  3

// Scratch: ping-pong propagation buffers + accumulator (3 x 25.6 MB)
__device__ float g_bufX[(size_t)N_NODES * EMB_DIM];
__device__ float g_bufY[(size_t)N_NODES * EMB_DIM];
__device__ float g_acc [(size_t)N_NODES * EMB_DIM];

// ---------------------------------------------------------------------------
// init: X = concat(user_emb, item_emb); acc = X; Y = 0
// One thread per float4 (N_NODES*EMB_DIM/4 = 1.6M threads)
// ---------------------------------------------------------------------------
__global__ void init_kernel(const float4* __restrict__ user_emb,
                            const float4* __restrict__ item_emb,
                            float4* __restrict__ X,
                            float4* __restrict__ Y,
                            float4* __restrict__ acc)
{
    const int n4 = N_NODES * EMB_DIM / 4;
    const int user4 = NUM_USERS * EMB_DIM / 4;
    for (int i = blockIdx.x * blockDim.x + threadIdx.x; i < n4;
         i += gridDim.x * blockDim.x) {
        float4 v = (i < user4) ? user_emb[i] : item_emb[i - user4];
        X[i] = v;
        acc[i] = v;
        Y[i] = make_float4(0.f, 0.f, 0.f, 0.f);
    }
}

// ---------------------------------------------------------------------------
// scatter: nxt[dst] += val * cur[src]   (warp per edge, lane = float2 slot)
// ---------------------------------------------------------------------------
__global__ void scatter_kernel(const float* __restrict__ cur,
                               float* __restrict__ nxt,
                               const float* __restrict__ edge_val,
                               const int*   __restrict__ edge_src,
                               const int*   __restrict__ edge_dst,
                               int nnz)
{
    int e = blockIdx.x * (blockDim.x >> 5) + (threadIdx.x >> 5);
    if (e >= nnz) return;
    const int lane = threadIdx.x & 31;

    const int   s = edge_src[e];
    const int   d = edge_dst[e];
    const float v = edge_val[e];

    const float2 m = reinterpret_cast<const float2*>(cur + (size_t)s * EMB_DIM)[lane];
    float* dst = nxt + (size_t)d * EMB_DIM + 2 * lane;
    atomicAdd(dst,     v * m.x);
    atomicAdd(dst + 1, v * m.y);
}

// ---------------------------------------------------------------------------
// acc += src_buf; zero_buf = 0   (fused accumulate + prepare next layer)
// ---------------------------------------------------------------------------
__global__ void accum_zero_kernel(float4* __restrict__ acc,
                                  const float4* __restrict__ src,
                                  float4* __restrict__ zero_buf)
{
    const int n4 = N_NODES * EMB_DIM / 4;
    for (int i = blockIdx.x * blockDim.x + threadIdx.x; i < n4;
         i += gridDim.x * blockDim.x) {
        float4 a = acc[i];
        float4 s = src[i];
        a.x += s.x; a.y += s.y; a.z += s.z; a.w += s.w;
        acc[i] = a;
        if (zero_buf) zero_buf[i] = make_float4(0.f, 0.f, 0.f, 0.f);
    }
}

// ---------------------------------------------------------------------------
// gamma[b] = (1/16) * dot(acc[users[b]], acc[NUM_USERS + items[b]])
// warp per batch element
// ---------------------------------------------------------------------------
__global__ void gamma_kernel(const float* __restrict__ acc,
                             const int* __restrict__ users,
                             const int* __restrict__ items,
                             float* __restrict__ out,
                             int batch)
{
    int b = blockIdx.x * (blockDim.x >> 5) + (threadIdx.x >> 5);
    if (b >= batch) return;
    const int lane = threadIdx.x & 31;

    const int u = users[b];
    const int it = items[b];

    const float2 a = reinterpret_cast<const float2*>(acc + (size_t)u * EMB_DIM)[lane];
    const float2 c = reinterpret_cast<const float2*>(
        acc + (size_t)(NUM_USERS + it) * EMB_DIM)[lane];

    float s = a.x * c.x + a.y * c.y;
    #pragma unroll
    for (int o = 16; o > 0; o >>= 1) s += __shfl_xor_sync(0xffffffffu, s, o);

    if (lane == 0) out[b] = s * (1.0f / 16.0f);  // (1/(L+1))^2 = 1/16
}

// ---------------------------------------------------------------------------
// launch
// ---------------------------------------------------------------------------
extern "C" void kernel_launch(void* const* d_in, const int* in_sizes, int n_in,
                              void* d_out, int out_size)
{
    const float* user_emb = (const float*)d_in[0];
    const float* item_emb = (const float*)d_in[1];
    const float* edge_val = (const float*)d_in[2];
    const int*   edge_src = (const int*)  d_in[3];
    const int*   edge_dst = (const int*)  d_in[4];
    const int*   users    = (const int*)  d_in[5];
    const int*   items    = (const int*)  d_in[6];
    const int nnz   = in_sizes[2];
    const int batch = in_sizes[5];
    float* out = (float*)d_out;

    float *X, *Y, *acc;
    cudaGetSymbolAddress((void**)&X,   g_bufX);
    cudaGetSymbolAddress((void**)&Y,   g_bufY);
    cudaGetSymbolAddress((void**)&acc, g_acc);

    const int n4 = N_NODES * EMB_DIM / 4;
    const int TB = 256;
    const int elem_blocks = (n4 + TB - 1) / TB;

    init_kernel<<<elem_blocks, TB>>>((const float4*)user_emb,
                                     (const float4*)item_emb,
                                     (float4*)X, (float4*)Y, (float4*)acc);

    const int warps_per_block = TB / 32;
    const int edge_blocks = (nnz + warps_per_block - 1) / warps_per_block;

    // Layer 1: X -> Y ; acc += Y ; zero X
    scatter_kernel<<<edge_blocks, TB>>>(X, Y, edge_val, edge_src, edge_dst, nnz);
    accum_zero_kernel<<<elem_blocks, TB>>>((float4*)acc, (const float4*)Y, (float4*)X);

    // Layer 2: Y -> X ; acc += X ; zero Y
    scatter_kernel<<<edge_blocks, TB>>>(Y, X, edge_val, edge_src, edge_dst, nnz);
    accum_zero_kernel<<<elem_blocks, TB>>>((float4*)acc, (const float4*)X, (float4*)Y);

    // Layer 3: X -> Y ; acc += Y (no zero needed)
    scatter_kernel<<<edge_blocks, TB>>>(X, Y, edge_val, edge_src, edge_dst, nnz);
    accum_zero_kernel<<<elem_blocks, TB>>>((float4*)acc, (const float4*)Y, nullptr);

    // Scoring
    const int gamma_blocks = (batch + warps_per_block - 1) / warps_per_block;
    gamma_kernel<<<gamma_blocks, TB>>>(acc, users, items, out, batch);
}

// round 3
// speedup vs baseline: 1.7436x; 1.7436x over previous
#include <cuda_runtime.h>
#include <cuda_bf16.h>
#include <cstdint>

// Problem constants (fixed by the reference)
#define NUM_USERS 50000
#define NUM_ITEMS 50000
#define N_NODES   (NUM_USERS + NUM_ITEMS)   // 100000
#define EMB_DIM   64
#define N_LAYERS  3

// Scratch: ping-pong propagation buffers + accumulator (3 x 25.6 MB)
__device__ float g_bufX[(size_t)N_NODES * EMB_DIM];
__device__ float g_bufY[(size_t)N_NODES * EMB_DIM];
__device__ float g_acc [(size_t)N_NODES * EMB_DIM];

// ---------------------------------------------------------------------------
// init: X = concat(user_emb, item_emb); acc = X; Y = 0
// ---------------------------------------------------------------------------
__global__ void init_kernel(const float4* __restrict__ user_emb,
                            const float4* __restrict__ item_emb,
                            float4* __restrict__ X,
                            float4* __restrict__ Y,
                            float4* __restrict__ acc)
{
    const int n4 = N_NODES * EMB_DIM / 4;
    const int user4 = NUM_USERS * EMB_DIM / 4;
    for (int i = blockIdx.x * blockDim.x + threadIdx.x; i < n4;
         i += gridDim.x * blockDim.x) {
        float4 v = (i < user4) ? user_emb[i] : item_emb[i - user4];
        X[i] = v;
        acc[i] = v;
        Y[i] = make_float4(0.f, 0.f, 0.f, 0.f);
    }
}

// ---------------------------------------------------------------------------
// scatter: nxt[dst] += val * cur[src]
// HALF-WARP per edge, lane = float4 slot (16 lanes x 16B = 256B row).
// Vector reduction red.global.add.v4.f32: 16 RED.128 per edge instead of
// 64 scalar atomics.
// ---------------------------------------------------------------------------
__global__ void scatter_kernel(const float* __restrict__ cur,
                               float* __restrict__ nxt,
                               const float* __restrict__ edge_val,
                               const int*   __restrict__ edge_src,
                               const int*   __restrict__ edge_dst,
                               int nnz)
{
    // 2 edges per warp: lanes [0,16) -> edge 2w, lanes [16,32) -> edge 2w+1
    const int warp = blockIdx.x * (blockDim.x >> 5) + (threadIdx.x >> 5);
    const int e = 2 * warp + ((threadIdx.x >> 4) & 1);
    if (e >= nnz) return;
    const int lane16 = threadIdx.x & 15;

    const int   s = edge_src[e];
    const int   d = edge_dst[e];
    const float v = edge_val[e];

    const float4 m = reinterpret_cast<const float4*>(
        cur + (size_t)s * EMB_DIM)[lane16];

    const float rx = v * m.x, ry = v * m.y, rz = v * m.z, rw = v * m.w;
    float* dst = nxt + (size_t)d * EMB_DIM + 4 * lane16;

    asm volatile("red.global.add.v4.f32 [%0], {%1, %2, %3, %4};"
                 :: "l"(dst), "f"(rx), "f"(ry), "f"(rz), "f"(rw)
                 : "memory");
}

// ---------------------------------------------------------------------------
// acc += src_buf; zero_buf = 0   (fused accumulate + prepare next layer)
// ---------------------------------------------------------------------------
__global__ void accum_zero_kernel(float4* __restrict__ acc,
                                  const float4* __restrict__ src,
                                  float4* __restrict__ zero_buf)
{
    const int n4 = N_NODES * EMB_DIM / 4;
    for (int i = blockIdx.x * blockDim.x + threadIdx.x; i < n4;
         i += gridDim.x * blockDim.x) {
        float4 a = acc[i];
        float4 s = src[i];
        a.x += s.x; a.y += s.y; a.z += s.z; a.w += s.w;
        acc[i] = a;
        if (zero_buf) zero_buf[i] = make_float4(0.f, 0.f, 0.f, 0.f);
    }
}

// ---------------------------------------------------------------------------
// gamma[b] = (1/16) * dot(acc[users[b]], acc[NUM_USERS + items[b]])
// warp per batch element
// ---------------------------------------------------------------------------
__global__ void gamma_kernel(const float* __restrict__ acc,
                             const int* __restrict__ users,
                             const int* __restrict__ items,
                             float* __restrict__ out,
                             int batch)
{
    int b = blockIdx.x * (blockDim.x >> 5) + (threadIdx.x >> 5);
    if (b >= batch) return;
    const int lane = threadIdx.x & 31;

    const int u = users[b];
    const int it = items[b];

    const float2 a = reinterpret_cast<const float2*>(acc + (size_t)u * EMB_DIM)[lane];
    const float2 c = reinterpret_cast<const float2*>(
        acc + (size_t)(NUM_USERS + it) * EMB_DIM)[lane];

    float s = a.x * c.x + a.y * c.y;
    #pragma unroll
    for (int o = 16; o > 0; o >>= 1) s += __shfl_xor_sync(0xffffffffu, s, o);

    if (lane == 0) out[b] = s * (1.0f / 16.0f);  // (1/(L+1))^2 = 1/16
}

// ---------------------------------------------------------------------------
// launch
// ---------------------------------------------------------------------------
extern "C" void kernel_launch(void* const* d_in, const int* in_sizes, int n_in,
                              void* d_out, int out_size)
{
    const float* user_emb = (const float*)d_in[0];
    const float* item_emb = (const float*)d_in[1];
    const float* edge_val = (const float*)d_in[2];
    const int*   edge_src = (const int*)  d_in[3];
    const int*   edge_dst = (const int*)  d_in[4];
    const int*   users    = (const int*)  d_in[5];
    const int*   items    = (const int*)  d_in[6];
    const int nnz   = in_sizes[2];
    const int batch = in_sizes[5];
    float* out = (float*)d_out;

    float *X, *Y, *acc;
    cudaGetSymbolAddress((void**)&X,   g_bufX);
    cudaGetSymbolAddress((void**)&Y,   g_bufY);
    cudaGetSymbolAddress((void**)&acc, g_acc);

    const int n4 = N_NODES * EMB_DIM / 4;
    const int TB = 256;
    const int elem_blocks = (n4 + TB - 1) / TB;

    init_kernel<<<elem_blocks, TB>>>((const float4*)user_emb,
                                     (const float4*)item_emb,
                                     (float4*)X, (float4*)Y, (float4*)acc);

    // 2 edges per warp -> 16 edges per 256-thread block
    const int edges_per_block = 2 * (TB / 32);
    const int edge_blocks = (nnz + edges_per_block - 1) / edges_per_block;

    // Layer 1: X -> Y ; acc += Y ; zero X
    scatter_kernel<<<edge_blocks, TB>>>(X, Y, edge_val, edge_src, edge_dst, nnz);
    accum_zero_kernel<<<elem_blocks, TB>>>((float4*)acc, (const float4*)Y, (float4*)X);

    // Layer 2: Y -> X ; acc += X ; zero Y
    scatter_kernel<<<edge_blocks, TB>>>(Y, X, edge_val, edge_src, edge_dst, nnz);
    accum_zero_kernel<<<elem_blocks, TB>>>((float4*)acc, (const float4*)X, (float4*)Y);

    // Layer 3: X -> Y ; acc += Y (no zero needed)
    scatter_kernel<<<edge_blocks, TB>>>(X, Y, edge_val, edge_src, edge_dst, nnz);
    accum_zero_kernel<<<elem_blocks, TB>>>((float4*)acc, (const float4*)Y, nullptr);

    // Scoring
    const int warps_per_block = TB / 32;
    const int gamma_blocks = (batch + warps_per_block - 1) / warps_per_block;
    gamma_kernel<<<gamma_blocks, TB>>>(acc, users, items, out, batch);
}

// round 6
// speedup vs baseline: 2.2170x; 1.2715x over previous
#include <cuda_runtime.h>
#include <cuda_bf16.h>
#include <cstdint>

// Problem constants (fixed by the reference)
#define NUM_USERS 50000
#define NUM_ITEMS 50000
#define N_NODES   (NUM_USERS + NUM_ITEMS)   // 100000
#define EMB_DIM   64
#define N_LAYERS  3
#define NNZ_MAX   3200000

// Scratch buffers (__device__ globals: allocation-guard safe)
__device__ float g_bufX[(size_t)N_NODES * EMB_DIM];
__device__ float g_bufY[(size_t)N_NODES * EMB_DIM];
__device__ float g_acc [(size_t)N_NODES * EMB_DIM];
__device__ int   g_ptr [N_NODES + 1];
__device__ int   g_pos [N_NODES];
__device__ int2  g_edges[NNZ_MAX];   // .x = src, .y = bitcast(val)

// ---------------------------------------------------------------------------
// zero destination-degree counters
// ---------------------------------------------------------------------------
__global__ void zero_pos_kernel(int* __restrict__ pos)
{
    for (int i = blockIdx.x * blockDim.x + threadIdx.x; i < N_NODES;
         i += gridDim.x * blockDim.x)
        pos[i] = 0;
}

// ---------------------------------------------------------------------------
// histogram of edge destinations
// ---------------------------------------------------------------------------
__global__ void hist_kernel(const int* __restrict__ edge_dst,
                            int* __restrict__ pos, int nnz)
{
    for (int e = blockIdx.x * blockDim.x + threadIdx.x; e < nnz;
         e += gridDim.x * blockDim.x)
        atomicAdd(&pos[edge_dst[e]], 1);
}

// ---------------------------------------------------------------------------
// single-block exclusive scan: counts (in g_pos) -> g_ptr; reset g_pos = ptr
// 1024 threads, each handling a contiguous chunk of ~98 counters.
// ---------------------------------------------------------------------------
__global__ void scan_kernel(int* __restrict__ pos, int* __restrict__ ptr)
{
    const int T = 1024;
    const int tid = threadIdx.x;
    const int chunk = (N_NODES + T - 1) / T;   // 98
    int start = tid * chunk;
    int end = start + chunk; if (end > N_NODES) end = N_NODES;

    int sum = 0;
    for (int i = start; i < end && start < N_NODES; ++i) sum += pos[i];

    __shared__ int sh[T];
    sh[tid] = sum;
    __syncthreads();
    // Hillis-Steele inclusive scan
    for (int d = 1; d < T; d <<= 1) {
        int v = (tid >= d) ? sh[tid - d] : 0;
        __syncthreads();
        sh[tid] += v;
        __syncthreads();
    }
    int run = sh[tid] - sum;   // exclusive prefix of this chunk

    if (start < N_NODES) {
        for (int i = start; i < end; ++i) {
            int c = pos[i];
            ptr[i] = run;
            pos[i] = run;      // cursor copy for bucket scatter
            run += c;
        }
        if (end == N_NODES) ptr[N_NODES] = run;
    }
}

// ---------------------------------------------------------------------------
// bucket scatter: edges -> dst-sorted (src, val) pairs
// ---------------------------------------------------------------------------
__global__ void bucket_kernel(const float* __restrict__ edge_val,
                              const int*   __restrict__ edge_src,
                              const int*   __restrict__ edge_dst,
                              int* __restrict__ pos,
                              int2* __restrict__ edges, int nnz)
{
    for (int e = blockIdx.x * blockDim.x + threadIdx.x; e < nnz;
         e += gridDim.x * blockDim.x) {
        int p = atomicAdd(&pos[edge_dst[e]], 1);
        edges[p] = make_int2(edge_src[e], __float_as_int(edge_val[e]));
    }
}

// ---------------------------------------------------------------------------
// init: X = concat(user_emb, item_emb); acc = X
// ---------------------------------------------------------------------------
__global__ void init_kernel(const float4* __restrict__ user_emb,
                            const float4* __restrict__ item_emb,
                            float4* __restrict__ X,
                            float4* __restrict__ acc)
{
    const int n4 = N_NODES * EMB_DIM / 4;
    const int user4 = NUM_USERS * EMB_DIM / 4;
    for (int i = blockIdx.x * blockDim.x + threadIdx.x; i < n4;
         i += gridDim.x * blockDim.x) {
        float4 v = (i < user4) ? user_emb[i] : item_emb[i - user4];
        X[i] = v;
        acc[i] = v;
    }
}

// ---------------------------------------------------------------------------
// pull layer: out[n] = sum_{e in bucket(n)} val_e * cur[src_e]
// warp per node, lane owns a float2 slot (32 x 8B = 256B row).
// Fuses acc += out; writes nxt only when needed. NO atomics.
// ---------------------------------------------------------------------------
__global__ void pull_kernel(const float2* __restrict__ cur,
                            float2* __restrict__ nxt,
                            float2* __restrict__ acc,
                            const int*  __restrict__ ptr,
                            const int2* __restrict__ edges,
                            int write_nxt)
{
    const int n = blockIdx.x * (blockDim.x >> 5) + (threadIdx.x >> 5);
    if (n >= N_NODES) return;
    const int lane = threadIdx.x & 31;

    const int beg = ptr[n];
    const int end = ptr[n + 1];

    float sx = 0.f, sy = 0.f;

    int i = beg;
    // unroll-by-4 for memory-level parallelism on the gathers
    for (; i + 3 < end; i += 4) {
        int2 e0 = edges[i],     e1 = edges[i + 1];
        int2 e2 = edges[i + 2], e3 = edges[i + 3];
        float2 m0 = cur[(size_t)e0.x * 32 + lane];
        float2 m1 = cur[(size_t)e1.x * 32 + lane];
        float2 m2 = cur[(size_t)e2.x * 32 + lane];
        float2 m3 = cur[(size_t)e3.x * 32 + lane];
        float v0 = __int_as_float(e0.y), v1 = __int_as_float(e1.y);
        float v2 = __int_as_float(e2.y), v3 = __int_as_float(e3.y);
        sx += v0 * m0.x + v1 * m1.x + v2 * m2.x + v3 * m3.x;
        sy += v0 * m0.y + v1 * m1.y + v2 * m2.y + v3 * m3.y;
    }
    for (; i < end; ++i) {
        int2 e = edges[i];
        float2 m = cur[(size_t)e.x * 32 + lane];
        float v = __int_as_float(e.y);
        sx += v * m.x;
        sy += v * m.y;
    }

    const size_t o = (size_t)n * 32 + lane;
    if (write_nxt) nxt[o] = make_float2(sx, sy);
    float2 a = acc[o];
    a.x += sx; a.y += sy;
    acc[o] = a;
}

// ---------------------------------------------------------------------------
// gamma[b] = (1/16) * dot(acc[users[b]], acc[NUM_USERS + items[b]])
// ---------------------------------------------------------------------------
__global__ void gamma_kernel(const float* __restrict__ acc,
                             const int* __restrict__ users,
                             const int* __restrict__ items,
                             float* __restrict__ out,
                             int batch)
{
    int b = blockIdx.x * (blockDim.x >> 5) + (threadIdx.x >> 5);
    if (b >= batch) return;
    const int lane = threadIdx.x & 31;

    const int u = users[b];
    const int it = items[b];

    const float2 a = reinterpret_cast<const float2*>(acc + (size_t)u * EMB_DIM)[lane];
    const float2 c = reinterpret_cast<const float2*>(
        acc + (size_t)(NUM_USERS + it) * EMB_DIM)[lane];

    float s = a.x * c.x + a.y * c.y;
    #pragma unroll
    for (int o = 16; o > 0; o >>= 1) s += __shfl_xor_sync(0xffffffffu, s, o);

    if (lane == 0) out[b] = s * (1.0f / 16.0f);  // (1/(L+1))^2 = 1/16
}

// ---------------------------------------------------------------------------
// launch
// ---------------------------------------------------------------------------
extern "C" void kernel_launch(void* const* d_in, const int* in_sizes, int n_in,
                              void* d_out, int out_size)
{
    const float* user_emb = (const float*)d_in[0];
    const float* item_emb = (const float*)d_in[1];
    const float* edge_val = (const float*)d_in[2];
    const int*   edge_src = (const int*)  d_in[3];
    const int*   edge_dst = (const int*)  d_in[4];
    const int*   users    = (const int*)  d_in[5];
    const int*   items    = (const int*)  d_in[6];
    const int nnz   = in_sizes[2];
    const int batch = in_sizes[5];
    float* out = (float*)d_out;

    float *X, *Y, *acc;
    int *ptr, *pos;
    int2 *edges;
    cudaGetSymbolAddress((void**)&X,     g_bufX);
    cudaGetSymbolAddress((void**)&Y,     g_bufY);
    cudaGetSymbolAddress((void**)&acc,   g_acc);
    cudaGetSymbolAddress((void**)&ptr,   g_ptr);
    cudaGetSymbolAddress((void**)&pos,   g_pos);
    cudaGetSymbolAddress((void**)&edges, g_edges);

    const int TB = 256;

    // ---- build dst-sorted CSR ----
    zero_pos_kernel<<<(N_NODES + TB - 1) / TB, TB>>>(pos);
    hist_kernel<<<(nnz + TB - 1) / TB, TB>>>(edge_dst, pos, nnz);
    scan_kernel<<<1, 1024>>>(pos, ptr);
    bucket_kernel<<<(nnz + TB - 1) / TB, TB>>>(edge_val, edge_src, edge_dst,
                                               pos, edges, nnz);

    // ---- init embeddings + accumulator ----
    const int n4 = N_NODES * EMB_DIM / 4;
    init_kernel<<<(n4 + TB - 1) / TB, TB>>>((const float4*)user_emb,
                                            (const float4*)item_emb,
                                            (float4*)X, (float4*)acc);

    // ---- 3 pull layers (warp per node) ----
    const int warps_per_block = TB / 32;
    const int node_blocks = (N_NODES + warps_per_block - 1) / warps_per_block;

    // Layer 1: X -> Y, acc += Y
    pull_kernel<<<node_blocks, TB>>>((const float2*)X, (float2*)Y, (float2*)acc,
                                     ptr, edges, 1);
    // Layer 2: Y -> X, acc += X
    pull_kernel<<<node_blocks, TB>>>((const float2*)Y, (float2*)X, (float2*)acc,
                                     ptr, edges, 1);
    // Layer 3: X -> (discard), acc += out only
    pull_kernel<<<node_blocks, TB>>>((const float2*)X, (float2*)Y, (float2*)acc,
                                     ptr, edges, 0);

    // ---- scoring ----
    const int gamma_blocks = (batch + warps_per_block - 1) / warps_per_block;
    gamma_kernel<<<gamma_blocks, TB>>>(acc, users, items, out, batch);
}

// round 12
// speedup vs baseline: 2.4128x; 1.0883x over previous
#include <cuda_runtime.h>
#include <cuda_fp16.h>
#include <cstdint>

// Problem constants (fixed by the reference)
#define NUM_USERS 50000
#define NUM_ITEMS 50000
#define N_NODES   (NUM_USERS + NUM_ITEMS)   // 100000
#define EMB_DIM   64
#define N_LAYERS  3
#define NNZ_MAX   3200000

// Scratch buffers (__device__ globals: allocation-guard safe)
// Propagation buffers in fp16 (half2 per 2 dims): 12.8 MB each
__device__ __half2 g_bufX[(size_t)N_NODES * (EMB_DIM / 2)];
__device__ __half2 g_bufY[(size_t)N_NODES * (EMB_DIM / 2)];
__device__ float   g_acc [(size_t)N_NODES * EMB_DIM];       // fp32 accumulator
__device__ int     g_ptr [N_NODES + 1];
__device__ int     g_pos [N_NODES];
__device__ int2    g_edges[NNZ_MAX];   // .x = src, .y = bitcast(val)

// ---------------------------------------------------------------------------
// zero destination-degree counters
// ---------------------------------------------------------------------------
__global__ void zero_pos_kernel(int* __restrict__ pos)
{
    for (int i = blockIdx.x * blockDim.x + threadIdx.x; i < N_NODES;
         i += gridDim.x * blockDim.x)
        pos[i] = 0;
}

// ---------------------------------------------------------------------------
// histogram of edge destinations
// ---------------------------------------------------------------------------
__global__ void hist_kernel(const int* __restrict__ edge_dst,
                            int* __restrict__ pos, int nnz)
{
    for (int e = blockIdx.x * blockDim.x + threadIdx.x; e < nnz;
         e += gridDim.x * blockDim.x)
        atomicAdd(&pos[edge_dst[e]], 1);
}

// ---------------------------------------------------------------------------
// single-block exclusive scan: counts (in g_pos) -> g_ptr; reset g_pos = ptr
// ---------------------------------------------------------------------------
__global__ void scan_kernel(int* __restrict__ pos, int* __restrict__ ptr)
{
    const int T = 1024;
    const int tid = threadIdx.x;
    const int chunk = (N_NODES + T - 1) / T;   // 98
    int start = tid * chunk;
    int end = start + chunk; if (end > N_NODES) end = N_NODES;

    int sum = 0;
    for (int i = start; i < end && start < N_NODES; ++i) sum += pos[i];

    __shared__ int sh[T];
    sh[tid] = sum;
    __syncthreads();
    for (int d = 1; d < T; d <<= 1) {
        int v = (tid >= d) ? sh[tid - d] : 0;
        __syncthreads();
        sh[tid] += v;
        __syncthreads();
    }
    int run = sh[tid] - sum;   // exclusive prefix of this chunk

    if (start < N_NODES) {
        for (int i = start; i < end; ++i) {
            int c = pos[i];
            ptr[i] = run;
            pos[i] = run;      // cursor copy for bucket scatter
            run += c;
        }
        if (end == N_NODES) ptr[N_NODES] = run;
    }
}

// ---------------------------------------------------------------------------
// bucket scatter: edges -> dst-sorted (src, val) pairs
// ---------------------------------------------------------------------------
__global__ void bucket_kernel(const float* __restrict__ edge_val,
                              const int*   __restrict__ edge_src,
                              const int*   __restrict__ edge_dst,
                              int* __restrict__ pos,
                              int2* __restrict__ edges, int nnz)
{
    for (int e = blockIdx.x * blockDim.x + threadIdx.x; e < nnz;
         e += gridDim.x * blockDim.x) {
        int p = atomicAdd(&pos[edge_dst[e]], 1);
        edges[p] = make_int2(edge_src[e], __float_as_int(edge_val[e]));
    }
}

// ---------------------------------------------------------------------------
// init: X = fp16(concat(user_emb, item_emb)); acc = fp32 concat
// thread i handles one float4 (4 dims) -> 2 half2
// ---------------------------------------------------------------------------
__global__ void init_kernel(const float4* __restrict__ user_emb,
                            const float4* __restrict__ item_emb,
                            __half2* __restrict__ X,
                            float4* __restrict__ acc)
{
    const int n4 = N_NODES * EMB_DIM / 4;
    const int user4 = NUM_USERS * EMB_DIM / 4;
    for (int i = blockIdx.x * blockDim.x + threadIdx.x; i < n4;
         i += gridDim.x * blockDim.x) {
        float4 v = (i < user4) ? user_emb[i] : item_emb[i - user4];
        acc[i] = v;
        X[2 * i]     = __float22half2_rn(make_float2(v.x, v.y));
        X[2 * i + 1] = __float22half2_rn(make_float2(v.z, v.w));
    }
}

// ---------------------------------------------------------------------------
// pull layer: out[n] = sum_{e in bucket(n)} val_e * cur[src_e]
// warp per node, lane owns one half2 slot (32 x 4B = 128B row).
// fp32 accumulation; fuses acc += out; writes fp16 nxt when needed.
// ---------------------------------------------------------------------------
__global__ void pull_kernel(const __half2* __restrict__ cur,
                            __half2* __restrict__ nxt,
                            float2* __restrict__ acc,
                            const int*  __restrict__ ptr,
                            const int2* __restrict__ edges,
                            int write_nxt)
{
    const int n = blockIdx.x * (blockDim.x >> 5) + (threadIdx.x >> 5);
    if (n >= N_NODES) return;
    const int lane = threadIdx.x & 31;

    const int beg = ptr[n];
    const int end = ptr[n + 1];

    float sx = 0.f, sy = 0.f;

    int i = beg;
    // unroll-by-4 for memory-level parallelism on the gathers
    for (; i + 3 < end; i += 4) {
        int2 e0 = edges[i],     e1 = edges[i + 1];
        int2 e2 = edges[i + 2], e3 = edges[i + 3];
        float2 m0 = __half22float2(cur[(size_t)e0.x * 32 + lane]);
        float2 m1 = __half22float2(cur[(size_t)e1.x * 32 + lane]);
        float2 m2 = __half22float2(cur[(size_t)e2.x * 32 + lane]);
        float2 m3 = __half22float2(cur[(size_t)e3.x * 32 + lane]);
        float v0 = __int_as_float(e0.y), v1 = __int_as_float(e1.y);
        float v2 = __int_as_float(e2.y), v3 = __int_as_float(e3.y);
        sx += v0 * m0.x + v1 * m1.x + v2 * m2.x + v3 * m3.x;
        sy += v0 * m0.y + v1 * m1.y + v2 * m2.y + v3 * m3.y;
    }
    for (; i < end; ++i) {
        int2 e = edges[i];
        float2 m = __half22float2(cur[(size_t)e.x * 32 + lane]);
        float v = __int_as_float(e.y);
        sx += v * m.x;
        sy += v * m.y;
    }

    const size_t o = (size_t)n * 32 + lane;
    if (write_nxt) nxt[o] = __float22half2_rn(make_float2(sx, sy));
    float2 a = acc[o];
    a.x += sx; a.y += sy;
    acc[o] = a;
}

// ---------------------------------------------------------------------------
// gamma[b] = (1/16) * dot(acc[users[b]], acc[NUM_USERS + items[b]])
// ---------------------------------------------------------------------------
__global__ void gamma_kernel(const float* __restrict__ acc,
                             const int* __restrict__ users,
                             const int* __restrict__ items,
                             float* __restrict__ out,
                             int batch)
{
    int b = blockIdx.x * (blockDim.x >> 5) + (threadIdx.x >> 5);
    if (b >= batch) return;
    const int lane = threadIdx.x & 31;

    const int u = users[b];
    const int it = items[b];

    const float2 a = reinterpret_cast<const float2*>(acc + (size_t)u * EMB_DIM)[lane];
    const float2 c = reinterpret_cast<const float2*>(
        acc + (size_t)(NUM_USERS + it) * EMB_DIM)[lane];

    float s = a.x * c.x + a.y * c.y;
    #pragma unroll
    for (int o = 16; o > 0; o >>= 1) s += __shfl_xor_sync(0xffffffffu, s, o);

    if (lane == 0) out[b] = s * (1.0f / 16.0f);  // (1/(L+1))^2 = 1/16
}

// ---------------------------------------------------------------------------
// launch
// ---------------------------------------------------------------------------
extern "C" void kernel_launch(void* const* d_in, const int* in_sizes, int n_in,
                              void* d_out, int out_size)
{
    const float* user_emb = (const float*)d_in[0];
    const float* item_emb = (const float*)d_in[1];
    const float* edge_val = (const float*)d_in[2];
    const int*   edge_src = (const int*)  d_in[3];
    const int*   edge_dst = (const int*)  d_in[4];
    const int*   users    = (const int*)  d_in[5];
    const int*   items    = (const int*)  d_in[6];
    const int nnz   = in_sizes[2];
    const int batch = in_sizes[5];
    float* out = (float*)d_out;

    __half2 *X, *Y;
    float *acc;
    int *ptr, *pos;
    int2 *edges;
    cudaGetSymbolAddress((void**)&X,     g_bufX);
    cudaGetSymbolAddress((void**)&Y,     g_bufY);
    cudaGetSymbolAddress((void**)&acc,   g_acc);
    cudaGetSymbolAddress((void**)&ptr,   g_ptr);
    cudaGetSymbolAddress((void**)&pos,   g_pos);
    cudaGetSymbolAddress((void**)&edges, g_edges);

    const int TB = 256;

    // ---- build dst-sorted CSR ----
    zero_pos_kernel<<<(N_NODES + TB - 1) / TB, TB>>>(pos);
    hist_kernel<<<(nnz + TB - 1) / TB, TB>>>(edge_dst, pos, nnz);
    scan_kernel<<<1, 1024>>>(pos, ptr);
    bucket_kernel<<<(nnz + TB - 1) / TB, TB>>>(edge_val, edge_src, edge_dst,
                                               pos, edges, nnz);

    // ---- init embeddings + accumulator ----
    const int n4 = N_NODES * EMB_DIM / 4;
    init_kernel<<<(n4 + TB - 1) / TB, TB>>>((const float4*)user_emb,
                                            (const float4*)item_emb,
                                            X, (float4*)acc);

    // ---- 3 pull layers (warp per node) ----
    const int warps_per_block = TB / 32;
    const int node_blocks = (N_NODES + warps_per_block - 1) / warps_per_block;

    // Layer 1: X -> Y, acc += Y
    pull_kernel<<<node_blocks, TB>>>(X, Y, (float2*)acc, ptr, edges, 1);
    // Layer 2: Y -> X, acc += X
    pull_kernel<<<node_blocks, TB>>>(Y, X, (float2*)acc, ptr, edges, 1);
    // Layer 3: X -> (discard), acc += out only
    pull_kernel<<<node_blocks, TB>>>(X, Y, (float2*)acc, ptr, edges, 0);

    // ---- scoring ----
    const int gamma_blocks = (batch + warps_per_block - 1) / warps_per_block;
    gamma_kernel<<<gamma_blocks, TB>>>(acc, users, items, out, batch);
}

// round 16
// speedup vs baseline: 2.7991x; 1.1601x over previous
#include <cuda_runtime.h>
#include <cuda_fp16.h>
#include <cstdint>

// Problem constants (fixed by the reference)
#define NUM_USERS 50000
#define NUM_ITEMS 50000
#define N_NODES   (NUM_USERS + NUM_ITEMS)   // 100000
#define EMB_DIM   64
#define N_LAYERS  3
#define NNZ_MAX   3200000

// Scratch buffers (__device__ globals: allocation-guard safe)
// Propagation buffers in fp16: row = 64 halves = 128 B = 8 x uint4
__device__ __half2 g_bufX[(size_t)N_NODES * (EMB_DIM / 2)];
__device__ __half2 g_bufY[(size_t)N_NODES * (EMB_DIM / 2)];
__device__ float   g_acc [(size_t)N_NODES * EMB_DIM];       // fp32 accumulator
__device__ int     g_ptr [N_NODES + 1];
__device__ int     g_pos [N_NODES];
__device__ int2    g_edges[NNZ_MAX];   // .x = src, .y = bitcast(val)

// ---------------------------------------------------------------------------
// zero destination-degree counters
// ---------------------------------------------------------------------------
__global__ void zero_pos_kernel(int* __restrict__ pos)
{
    for (int i = blockIdx.x * blockDim.x + threadIdx.x; i < N_NODES;
         i += gridDim.x * blockDim.x)
        pos[i] = 0;
}

// ---------------------------------------------------------------------------
// histogram of edge destinations
// ---------------------------------------------------------------------------
__global__ void hist_kernel(const int* __restrict__ edge_dst,
                            int* __restrict__ pos, int nnz)
{
    for (int e = blockIdx.x * blockDim.x + threadIdx.x; e < nnz;
         e += gridDim.x * blockDim.x)
        atomicAdd(&pos[edge_dst[e]], 1);
}

// ---------------------------------------------------------------------------
// single-block exclusive scan: counts (in g_pos) -> g_ptr; reset g_pos = ptr
// ---------------------------------------------------------------------------
__global__ void scan_kernel(int* __restrict__ pos, int* __restrict__ ptr)
{
    const int T = 1024;
    const int tid = threadIdx.x;
    const int chunk = (N_NODES + T - 1) / T;   // 98
    int start = tid * chunk;
    int end = start + chunk; if (end > N_NODES) end = N_NODES;

    int sum = 0;
    for (int i = start; i < end && start < N_NODES; ++i) sum += pos[i];

    __shared__ int sh[T];
    sh[tid] = sum;
    __syncthreads();
    for (int d = 1; d < T; d <<= 1) {
        int v = (tid >= d) ? sh[tid - d] : 0;
        __syncthreads();
        sh[tid] += v;
        __syncthreads();
    }
    int run = sh[tid] - sum;   // exclusive prefix of this chunk

    if (start < N_NODES) {
        for (int i = start; i < end; ++i) {
            int c = pos[i];
            ptr[i] = run;
            pos[i] = run;      // cursor copy for bucket scatter
            run += c;
        }
        if (end == N_NODES) ptr[N_NODES] = run;
    }
}

// ---------------------------------------------------------------------------
// bucket scatter: edges -> dst-sorted (src, val) pairs
// ---------------------------------------------------------------------------
__global__ void bucket_kernel(const float* __restrict__ edge_val,
                              const int*   __restrict__ edge_src,
                              const int*   __restrict__ edge_dst,
                              int* __restrict__ pos,
                              int2* __restrict__ edges, int nnz)
{
    for (int e = blockIdx.x * blockDim.x + threadIdx.x; e < nnz;
         e += gridDim.x * blockDim.x) {
        int p = atomicAdd(&pos[edge_dst[e]], 1);
        edges[p] = make_int2(edge_src[e], __float_as_int(edge_val[e]));
    }
}

// ---------------------------------------------------------------------------
// init: X = fp16(concat(user_emb, item_emb)); acc = fp32 concat
// ---------------------------------------------------------------------------
__global__ void init_kernel(const float4* __restrict__ user_emb,
                            const float4* __restrict__ item_emb,
                            __half2* __restrict__ X,
                            float4* __restrict__ acc)
{
    const int n4 = N_NODES * EMB_DIM / 4;
    const int user4 = NUM_USERS * EMB_DIM / 4;
    for (int i = blockIdx.x * blockDim.x + threadIdx.x; i < n4;
         i += gridDim.x * blockDim.x) {
        float4 v = (i < user4) ? user_emb[i] : item_emb[i - user4];
        acc[i] = v;
        X[2 * i]     = __float22half2_rn(make_float2(v.x, v.y));
        X[2 * i + 1] = __float22half2_rn(make_float2(v.z, v.w));
    }
}

// ---------------------------------------------------------------------------
// accumulate 8 halves (one uint4 = 4 x half2) scaled by v into s[8]
// ---------------------------------------------------------------------------
__device__ __forceinline__ void accum8(float* __restrict__ s, uint4 m, float v)
{
    float2 f;
    f = __half22float2(*reinterpret_cast<__half2*>(&m.x)); s[0] += v * f.x; s[1] += v * f.y;
    f = __half22float2(*reinterpret_cast<__half2*>(&m.y)); s[2] += v * f.x; s[3] += v * f.y;
    f = __half22float2(*reinterpret_cast<__half2*>(&m.z)); s[4] += v * f.x; s[5] += v * f.y;
    f = __half22float2(*reinterpret_cast<__half2*>(&m.w)); s[6] += v * f.x; s[7] += v * f.y;
}

// ---------------------------------------------------------------------------
// pull layer: out[n] = sum_{e in bucket(n)} val_e * cur[src_e]
// 4 nodes per warp: 8-lane group per node, lane owns 8 dims (one uint4, 16B).
// One warp-wide gather LDG serves 4 edges -> 4x fewer LDG instructions.
// fp32 accumulation; fuses acc += out; writes fp16 nxt when needed.
// ---------------------------------------------------------------------------
__global__ void pull_kernel(const uint4* __restrict__ cur,   // 8 uint4 per node row
                            uint4* __restrict__ nxt,
                            float4* __restrict__ acc,        // 16 float4 per node
                            const int*  __restrict__ ptr,
                            const int2* __restrict__ edges,
                            int write_nxt)
{
    const int warp = blockIdx.x * (blockDim.x >> 5) + (threadIdx.x >> 5);
    const int lane = threadIdx.x & 31;
    const int grp  = lane >> 3;        // 0..3 : node within warp
    const int sub  = lane & 7;         // 0..7 : 16B slot within row
    const int n = warp * 4 + grp;
    if (n >= N_NODES) return;

    const int beg = ptr[n];
    const int end = ptr[n + 1];

    float s[8] = {0.f, 0.f, 0.f, 0.f, 0.f, 0.f, 0.f, 0.f};

    int i = beg;
    // unroll-by-2 for MLP on the gathers
    for (; i + 1 < end; i += 2) {
        int2 e0 = edges[i];
        int2 e1 = edges[i + 1];
        uint4 m0 = cur[(size_t)e0.x * 8 + sub];
        uint4 m1 = cur[(size_t)e1.x * 8 + sub];
        accum8(s, m0, __int_as_float(e0.y));
        accum8(s, m1, __int_as_float(e1.y));
    }
    if (i < end) {
        int2 e = edges[i];
        uint4 m = cur[(size_t)e.x * 8 + sub];
        accum8(s, m, __int_as_float(e.y));
    }

    // lane sub owns dims [8*sub, 8*sub+8)
    if (write_nxt) {
        uint4 p;
        __half2 h;
        h = __float22half2_rn(make_float2(s[0], s[1])); p.x = *reinterpret_cast<unsigned*>(&h);
        h = __float22half2_rn(make_float2(s[2], s[3])); p.y = *reinterpret_cast<unsigned*>(&h);
        h = __float22half2_rn(make_float2(s[4], s[5])); p.z = *reinterpret_cast<unsigned*>(&h);
        h = __float22half2_rn(make_float2(s[6], s[7])); p.w = *reinterpret_cast<unsigned*>(&h);
        nxt[(size_t)n * 8 + sub] = p;
    }

    const size_t o = (size_t)n * 16 + 2 * sub;
    float4 a0 = acc[o];
    float4 a1 = acc[o + 1];
    a0.x += s[0]; a0.y += s[1]; a0.z += s[2]; a0.w += s[3];
    a1.x += s[4]; a1.y += s[5]; a1.z += s[6]; a1.w += s[7];
    acc[o]     = a0;
    acc[o + 1] = a1;
}

// ---------------------------------------------------------------------------
// gamma[b] = (1/16) * dot(acc[users[b]], acc[NUM_USERS + items[b]])
// ---------------------------------------------------------------------------
__global__ void gamma_kernel(const float* __restrict__ acc,
                             const int* __restrict__ users,
                             const int* __restrict__ items,
                             float* __restrict__ out,
                             int batch)
{
    int b = blockIdx.x * (blockDim.x >> 5) + (threadIdx.x >> 5);
    if (b >= batch) return;
    const int lane = threadIdx.x & 31;

    const int u = users[b];
    const int it = items[b];

    const float2 a = reinterpret_cast<const float2*>(acc + (size_t)u * EMB_DIM)[lane];
    const float2 c = reinterpret_cast<const float2*>(
        acc + (size_t)(NUM_USERS + it) * EMB_DIM)[lane];

    float s = a.x * c.x + a.y * c.y;
    #pragma unroll
    for (int o = 16; o > 0; o >>= 1) s += __shfl_xor_sync(0xffffffffu, s, o);

    if (lane == 0) out[b] = s * (1.0f / 16.0f);  // (1/(L+1))^2 = 1/16
}

// ---------------------------------------------------------------------------
// launch
// ---------------------------------------------------------------------------
extern "C" void kernel_launch(void* const* d_in, const int* in_sizes, int n_in,
                              void* d_out, int out_size)
{
    const float* user_emb = (const float*)d_in[0];
    const float* item_emb = (const float*)d_in[1];
    const float* edge_val = (const float*)d_in[2];
    const int*   edge_src = (const int*)  d_in[3];
    const int*   edge_dst = (const int*)  d_in[4];
    const int*   users    = (const int*)  d_in[5];
    const int*   items    = (const int*)  d_in[6];
    const int nnz   = in_sizes[2];
    const int batch = in_sizes[5];
    float* out = (float*)d_out;

    __half2 *X, *Y;
    float *acc;
    int *ptr, *pos;
    int2 *edges;
    cudaGetSymbolAddress((void**)&X,     g_bufX);
    cudaGetSymbolAddress((void**)&Y,     g_bufY);
    cudaGetSymbolAddress((void**)&acc,   g_acc);
    cudaGetSymbolAddress((void**)&ptr,   g_ptr);
    cudaGetSymbolAddress((void**)&pos,   g_pos);
    cudaGetSymbolAddress((void**)&edges, g_edges);

    const int TB = 256;

    // ---- build dst-sorted CSR ----
    zero_pos_kernel<<<(N_NODES + TB - 1) / TB, TB>>>(pos);
    hist_kernel<<<(nnz + TB - 1) / TB, TB>>>(edge_dst, pos, nnz);
    scan_kernel<<<1, 1024>>>(pos, ptr);
    bucket_kernel<<<(nnz + TB - 1) / TB, TB>>>(edge_val, edge_src, edge_dst,
                                               pos, edges, nnz);

    // ---- init embeddings + accumulator ----
    const int n4 = N_NODES * EMB_DIM / 4;
    init_kernel<<<(n4 + TB - 1) / TB, TB>>>((const float4*)user_emb,
                                            (const float4*)item_emb,
                                            X, (float4*)acc);

    // ---- 3 pull layers (4 nodes per warp, 8 lanes per node) ----
    const int warps_per_block = TB / 32;                  // 8
    const int nodes_per_block = 4 * warps_per_block;      // 32
    const int node_blocks = (N_NODES + nodes_per_block - 1) / nodes_per_block;

    // Layer 1: X -> Y, acc += Y
    pull_kernel<<<node_blocks, TB>>>((const uint4*)X, (uint4*)Y, (float4*)acc,
                                     ptr, edges, 1);
    // Layer 2: Y -> X, acc += X
    pull_kernel<<<node_blocks, TB>>>((const uint4*)Y, (uint4*)X, (float4*)acc,
                                     ptr, edges, 1);
    // Layer 3: X -> (discard), acc += out only
    pull_kernel<<<node_blocks, TB>>>((const uint4*)X, (uint4*)Y, (float4*)acc,
                                     ptr, edges, 0);

    // ---- scoring ----
    const int gamma_blocks = (batch + warps_per_block - 1) / warps_per_block;
    gamma_kernel<<<gamma_blocks, TB>>>(acc, users, items, out, batch);
}